// round 7
// baseline (speedup 1.0000x reference)
#include <cuda_runtime.h>
#include <math.h>
#include <stdint.h>

#define NVW 4
#define B_ 4
#define N_ 256
#define C_ 768
#define H_ 12
#define HD_ 64
#define HID_ 3072
#define MROWS (B_*N_)   // 1024 rows per view

// ---------------- scratch (device globals; no allocation) ----------------
__device__ float g_Xn [NVW*MROWS*C_];
__device__ float g_qkv[NVW*MROWS*3*C_];
__device__ float g_ctx[NVW*MROWS*C_];
__device__ float g_x  [NVW*MROWS*C_];
__device__ float g_hn [NVW*MROWS*C_];
__device__ float g_h1 [NVW*MROWS*HID_];
__device__ float g_x2 [NVW*MROWS*C_];
__device__ float g_kv [NVW*MROWS*2*C_];
__device__ float g_qh [NVW*C_];
__device__ float g_c2 [NVW*B_*C_];

__device__ __forceinline__ float gelu_exact(float x) {
    return 0.5f * x * (1.0f + erff(x * 0.70710678118654752f));
}

__device__ __forceinline__ float to_tf32(float x) {
    float r;
    asm("cvt.rna.tf32.f32 %0, %1;" : "=f"(r) : "f"(x));
    return r;
}

#define MMA_TF32(d, a, b) \
    asm volatile( \
        "mma.sync.aligned.m16n8k8.row.col.f32.tf32.tf32.f32 " \
        "{%0,%1,%2,%3}, {%4,%5,%6,%7}, {%8,%9}, {%0,%1,%2,%3};" \
        : "+f"((d)[0]), "+f"((d)[1]), "+f"((d)[2]), "+f"((d)[3]) \
        : "r"((a)[0]), "r"((a)[1]), "r"((a)[2]), "r"((a)[3]), \
          "r"((b)[0]), "r"((b)[1]))

// ---------------- LayerNorm ----------------
__global__ __launch_bounds__(256) void ln_kernel(
    const float* __restrict__ X, const float* __restrict__ g,
    const float* __restrict__ be, float* __restrict__ Y,
    int remap, int pervw)
{
    int r = blockIdx.x;
    int v = r / (B_ * N_);
    long inrow;
    if (remap) {
        int rem = r % (B_ * N_);
        int bb = rem / N_;
        int n  = rem % N_;
        inrow = ((long)(bb * NVW + v) * N_ + n);
    } else {
        inrow = r;
    }
    const float* x = X + inrow * C_;
    float* y = Y + (long)r * C_;
    const float* gg = g  + (pervw ? v * C_ : 0);
    const float* bb2 = be + (pervw ? v * C_ : 0);

    int t = threadIdx.x;
    float v0 = x[t], v1 = x[t + 256], v2 = x[t + 512];
    float s  = v0 + v1 + v2;
    float sq = v0 * v0 + v1 * v1 + v2 * v2;

    __shared__ float rs[256], rq[256];
    rs[t] = s; rq[t] = sq;
    __syncthreads();
    for (int off = 128; off > 0; off >>= 1) {
        if (t < off) { rs[t] += rs[t + off]; rq[t] += rq[t + off]; }
        __syncthreads();
    }
    float mean = rs[0] * (1.0f / C_);
    float var  = rq[0] * (1.0f / C_) - mean * mean;
    float rstd = rsqrtf(var + 1e-6f);

    y[t]       = (v0 - mean) * rstd * gg[t]       + bb2[t];
    y[t + 256] = (v1 - mean) * rstd * gg[t + 256] + bb2[t + 256];
    y[t + 512] = (v2 - mean) * rstd * gg[t + 512] + bb2[t + 512];
}

// ---------------- 3xTF32 mma.sync batched NT GEMM (v2) ----------------
// CTA tile 128x128, 512 threads, 16 warps (4x4), warp tile 32x32.
// hi/lo precomputed at staging into 4 smem tiles [k][row] stride 136.
// Double-buffered; one __syncthreads per K-chunk of 32.
#define KC 32
#define SROW 136
#define TILE_F (KC * SROW)                  // 4352 floats per tile
#define GEMM_SMEM (2 * 4 * TILE_F * 4)      // 139264 bytes

__global__ void __launch_bounds__(512, 1)
gemm_mma(const float* __restrict__ A, const float* __restrict__ W,
         const float* __restrict__ bias, const float* __restrict__ res,
         float* __restrict__ Cout, int Kdim, int D,
         long sA, long sW, long sB, long sR, long sC, float alpha, int act)
{
    extern __shared__ float sm[];
    const int v = blockIdx.z;
    const float* Av = A + (long)v * sA;
    const float* Wv = W + (long)v * sW;
    float* Cv = Cout + (long)v * sC;
    const int bm = blockIdx.y * 128, bn = blockIdx.x * 128;

    const int t = threadIdx.x, lane = t & 31, wid = t >> 5;
    const int wm = (wid >> 2) * 32;    // warp row offset (4 groups)
    const int wn = (wid & 3) * 32;     // warp col offset (4 groups)

    const int srow = t & 127;          // staging row
    const int k4b = t >> 7;            // 0..3

    const int fr = lane >> 2;          // 0..7
    const int fk = lane & 3;           // 0..3

    float acc[2][4][4];
    #pragma unroll
    for (int a = 0; a < 2; a++)
        #pragma unroll
        for (int b = 0; b < 4; b++)
            #pragma unroll
            for (int c = 0; c < 4; c++) acc[a][b][c] = 0.0f;

    float4 aR[2], wR[2];
    const int steps = Kdim / KC;

    // ---- preload + stage chunk 0 ----
    {
        const float* Ap = Av + (long)(bm + srow) * Kdim;
        const float* Wp = Wv + (long)(bn + srow) * Kdim;
        #pragma unroll
        for (int s = 0; s < 2; s++) {
            int k4 = k4b + 4 * s;
            aR[s] = *(const float4*)(Ap + k4 * 4);
            wR[s] = *(const float4*)(Wp + k4 * 4);
        }
        float* Ahi = sm;
        float* Alo = Ahi + TILE_F;
        float* Whi = Alo + TILE_F;
        float* Wlo = Whi + TILE_F;
        #pragma unroll
        for (int s = 0; s < 2; s++) {
            int k = (k4b + 4 * s) * 4;
            float av[4] = {aR[s].x, aR[s].y, aR[s].z, aR[s].w};
            float wv[4] = {wR[s].x, wR[s].y, wR[s].z, wR[s].w};
            #pragma unroll
            for (int i = 0; i < 4; i++) {
                float ah = to_tf32(av[i]);
                float wh = to_tf32(wv[i]);
                Ahi[(k + i) * SROW + srow] = ah;
                Alo[(k + i) * SROW + srow] = to_tf32(av[i] - ah);
                Whi[(k + i) * SROW + srow] = wh;
                Wlo[(k + i) * SROW + srow] = to_tf32(wv[i] - wh);
            }
        }
    }
    __syncthreads();

    for (int c = 0; c < steps; c++) {
        bool more = (c + 1 < steps);
        if (more) {
            const float* Ap = Av + (long)(bm + srow) * Kdim + (c + 1) * KC;
            const float* Wp = Wv + (long)(bn + srow) * Kdim + (c + 1) * KC;
            #pragma unroll
            for (int s = 0; s < 2; s++) {
                int k4 = k4b + 4 * s;
                aR[s] = *(const float4*)(Ap + k4 * 4);
                wR[s] = *(const float4*)(Wp + k4 * 4);
            }
        }

        const float* Ahi = sm + (c & 1) * 4 * TILE_F;
        const float* Alo = Ahi + TILE_F;
        const float* Whi = Alo + TILE_F;
        const float* Wlo = Whi + TILE_F;

        #pragma unroll
        for (int kk = 0; kk < 4; kk++) {
            int k0 = kk * 8 + fk;
            uint32_t ah[2][4], al[2][4], bh[4][2], bl[4][2];
            #pragma unroll
            for (int mt = 0; mt < 2; mt++) {
                int r0 = wm + mt * 16 + fr;
                // a0=A[fr][fk], a1=A[fr+8][fk], a2=A[fr][fk+4], a3=A[fr+8][fk+4]
                ah[mt][0] = __float_as_uint(Ahi[(k0    ) * SROW + r0]);
                ah[mt][1] = __float_as_uint(Ahi[(k0    ) * SROW + r0 + 8]);
                ah[mt][2] = __float_as_uint(Ahi[(k0 + 4) * SROW + r0]);
                ah[mt][3] = __float_as_uint(Ahi[(k0 + 4) * SROW + r0 + 8]);
                al[mt][0] = __float_as_uint(Alo[(k0    ) * SROW + r0]);
                al[mt][1] = __float_as_uint(Alo[(k0    ) * SROW + r0 + 8]);
                al[mt][2] = __float_as_uint(Alo[(k0 + 4) * SROW + r0]);
                al[mt][3] = __float_as_uint(Alo[(k0 + 4) * SROW + r0 + 8]);
            }
            #pragma unroll
            for (int nt = 0; nt < 4; nt++) {
                int n0 = wn + nt * 8 + fr;
                bh[nt][0] = __float_as_uint(Whi[(k0    ) * SROW + n0]);
                bh[nt][1] = __float_as_uint(Whi[(k0 + 4) * SROW + n0]);
                bl[nt][0] = __float_as_uint(Wlo[(k0    ) * SROW + n0]);
                bl[nt][1] = __float_as_uint(Wlo[(k0 + 4) * SROW + n0]);
            }
            #pragma unroll
            for (int mt = 0; mt < 2; mt++)
                #pragma unroll
                for (int nt = 0; nt < 4; nt++) {
                    MMA_TF32(acc[mt][nt], ah[mt], bh[nt]);
                    MMA_TF32(acc[mt][nt], ah[mt], bl[nt]);
                    MMA_TF32(acc[mt][nt], al[mt], bh[nt]);
                }
        }

        if (more) {
            float* Ahi2 = sm + ((c + 1) & 1) * 4 * TILE_F;
            float* Alo2 = Ahi2 + TILE_F;
            float* Whi2 = Alo2 + TILE_F;
            float* Wlo2 = Whi2 + TILE_F;
            #pragma unroll
            for (int s = 0; s < 2; s++) {
                int k = (k4b + 4 * s) * 4;
                float av[4] = {aR[s].x, aR[s].y, aR[s].z, aR[s].w};
                float wv[4] = {wR[s].x, wR[s].y, wR[s].z, wR[s].w};
                #pragma unroll
                for (int i = 0; i < 4; i++) {
                    float ahh = to_tf32(av[i]);
                    float whh = to_tf32(wv[i]);
                    Ahi2[(k + i) * SROW + srow] = ahh;
                    Alo2[(k + i) * SROW + srow] = to_tf32(av[i] - ahh);
                    Whi2[(k + i) * SROW + srow] = whh;
                    Wlo2[(k + i) * SROW + srow] = to_tf32(wv[i] - whh);
                }
            }
        }
        __syncthreads();
    }

    // epilogue: c0,c1 -> (row, 2fk..2fk+1); c2,c3 -> row+8
    #pragma unroll
    for (int mt = 0; mt < 2; mt++) {
        #pragma unroll
        for (int nt = 0; nt < 4; nt++) {
            int row = bm + wm + mt * 16 + fr;
            int col = bn + wn + nt * 8 + 2 * fk;
            float b0 = 0.f, b1 = 0.f;
            if (bias) {
                b0 = bias[(long)v * sB + col];
                b1 = bias[(long)v * sB + col + 1];
            }
            #pragma unroll
            for (int half = 0; half < 2; half++) {
                int r = row + half * 8;
                float v0 = alpha * (acc[mt][nt][half * 2 + 0] + b0);
                float v1 = alpha * (acc[mt][nt][half * 2 + 1] + b1);
                if (act == 1) { v0 = gelu_exact(v0); v1 = gelu_exact(v1); }
                if (res) {
                    v0 += res[(long)v * sR + (long)r * D + col];
                    v1 += res[(long)v * sR + (long)r * D + col + 1];
                }
                float2 o2 = {v0, v1};
                *(float2*)&Cv[(long)r * D + col] = o2;
            }
        }
    }
}

// ---------------- Pairwise cross-view attention with mean over j ----------------
__global__ __launch_bounds__(256) void attn_kernel(
    const float* __restrict__ qkv, float* __restrict__ ctx_out)
{
    int h = blockIdx.x, b = blockIdx.y, i = blockIdx.z;
    int n = threadIdx.x;
    const float scale = 0.125f;

    __shared__ __align__(16) float sKV[64 * 64];

    float q[64];
    const float* qptr = qkv + ((long)((i * B_ + b) * N_ + n)) * (3 * C_) + h * HD_;
    #pragma unroll
    for (int e4 = 0; e4 < 16; e4++) {
        float4 t4 = *(const float4*)(qptr + e4 * 4);
        q[e4 * 4 + 0] = t4.x; q[e4 * 4 + 1] = t4.y;
        q[e4 * 4 + 2] = t4.z; q[e4 * 4 + 3] = t4.w;
    }

    float ctx[64];
    #pragma unroll
    for (int e = 0; e < 64; e++) ctx[e] = 0.0f;

    float sloc[256];

    for (int j = 0; j < NVW; j++) {
        const float* kbase = qkv + ((long)((j * B_ + b) * N_)) * (3 * C_) + C_ + h * HD_;
        const float* vbase = kbase + C_;

        float smax = -1e30f;
        for (int c = 0; c < 4; c++) {
            __syncthreads();
            #pragma unroll
            for (int r = 0; r < 4; r++) {
                int F = threadIdx.x + 256 * r;
                int row  = F >> 4;
                int col4 = (F & 15) << 2;
                float4 t4 = *(const float4*)(kbase + (long)(c * 64 + row) * (3 * C_) + col4);
                *(float4*)&sKV[row * 64 + col4] = t4;
            }
            __syncthreads();
            for (int m = 0; m < 64; m++) {
                float d0 = 0.f, d1 = 0.f, d2 = 0.f, d3 = 0.f;
                const float* kr = &sKV[m * 64];
                #pragma unroll
                for (int e = 0; e < 64; e += 4) {
                    d0 += q[e + 0] * kr[e + 0];
                    d1 += q[e + 1] * kr[e + 1];
                    d2 += q[e + 2] * kr[e + 2];
                    d3 += q[e + 3] * kr[e + 3];
                }
                float s = ((d0 + d1) + (d2 + d3)) * scale;
                sloc[c * 64 + m] = s;
                smax = fmaxf(smax, s);
            }
        }
        float ssum = 0.0f;
        for (int m = 0; m < 256; m++) {
            float e_ = __expf(sloc[m] - smax);
            sloc[m] = e_;
            ssum += e_;
        }
        float inv = 1.0f / ssum;

        for (int c = 0; c < 4; c++) {
            __syncthreads();
            #pragma unroll
            for (int r = 0; r < 4; r++) {
                int F = threadIdx.x + 256 * r;
                int row  = F >> 4;
                int col4 = (F & 15) << 2;
                float4 t4 = *(const float4*)(vbase + (long)(c * 64 + row) * (3 * C_) + col4);
                *(float4*)&sKV[row * 64 + col4] = t4;
            }
            __syncthreads();
            for (int m = 0; m < 64; m++) {
                float pm = sloc[c * 64 + m] * inv;
                const float* vr = &sKV[m * 64];
                #pragma unroll
                for (int e = 0; e < 64; e++) ctx[e] += pm * vr[e];
            }
        }
    }

    float* outp = ctx_out + ((long)((i * B_ + b) * N_ + n)) * C_ + h * HD_;
    #pragma unroll
    for (int e4 = 0; e4 < 16; e4++) {
        float4 o4;
        o4.x = ctx[e4 * 4 + 0] * 0.25f;
        o4.y = ctx[e4 * 4 + 1] * 0.25f;
        o4.z = ctx[e4 * 4 + 2] * 0.25f;
        o4.w = ctx[e4 * 4 + 3] * 0.25f;
        *(float4*)(outp + e4 * 4) = o4;
    }
}

// ---------------- learnable-query projection ----------------
__global__ __launch_bounds__(256) void qh_kernel(
    const float* __restrict__ query, const float* __restrict__ w,
    const float* __restrict__ bq, float* __restrict__ qh)
{
    int v = blockIdx.x;
    int t = threadIdx.x;
    for (int d = t; d < C_; d += 256) {
        const float* wr = w + (long)v * (3 * C_) * C_ + (long)d * C_;
        float acc = 0.0f;
        #pragma unroll 4
        for (int c = 0; c < C_; c++) acc += query[c] * wr[c];
        qh[v * C_ + d] = acc + bq[(long)v * (3 * C_) + d];
    }
}

// ---------------- cross attention (single query) ----------------
__global__ __launch_bounds__(256) void cross_attn_kernel(
    const float* __restrict__ kv, const float* __restrict__ qh,
    float* __restrict__ c2)
{
    int h = blockIdx.x, b = blockIdx.y, v = blockIdx.z;
    int t = threadIdx.x;

    __shared__ float p[256];
    __shared__ float red[256];
    __shared__ float part[4][64];

    const float* kvb = kv + ((long)(v * B_ + b) * N_) * (2 * C_);
    const float* qhp = qh + v * C_ + h * HD_;
    const float* krow = kvb + (long)t * (2 * C_) + h * HD_;

    float s = 0.0f;
    #pragma unroll
    for (int e = 0; e < 64; e++) s += qhp[e] * krow[e];
    s *= 0.125f;

    red[t] = s; __syncthreads();
    for (int off = 128; off > 0; off >>= 1) {
        if (t < off) red[t] = fmaxf(red[t], red[t + off]);
        __syncthreads();
    }
    float mx = red[0];
    __syncthreads();

    float e_ = __expf(s - mx);
    p[t] = e_; red[t] = e_;
    __syncthreads();
    for (int off = 128; off > 0; off >>= 1) {
        if (t < off) red[t] += red[t + off];
        __syncthreads();
    }
    float inv = 1.0f / red[0];
    __syncthreads();

    int e = t & 63, pid = t >> 6;
    float acc = 0.0f;
    for (int n = pid * 64; n < pid * 64 + 64; n++)
        acc += p[n] * kvb[(long)n * (2 * C_) + C_ + h * HD_ + e];
    part[pid][e] = acc;
    __syncthreads();
    if (t < 64) {
        float r = (part[0][t] + part[1][t]) + (part[2][t] + part[3][t]);
        c2[(long)(v * B_ + b) * C_ + h * HD_ + t] = r * inv;
    }
}

// ---------------- output projection + broadcast over N ----------------
__global__ __launch_bounds__(256) void out_kernel(
    const float* __restrict__ c2, const float* __restrict__ w,
    const float* __restrict__ bias, float* __restrict__ out)
{
    int v = blockIdx.x, b = blockIdx.y;
    int t = threadIdx.x;

    __shared__ float sc[C_];
    for (int c = t; c < C_; c += 256) sc[c] = c2[(long)(v * B_ + b) * C_ + c];
    __syncthreads();

    float o[3];
    #pragma unroll
    for (int r = 0; r < 3; r++) {
        int co = t + r * 256;
        const float* wr = w + (long)v * C_ * C_ + (long)co * C_;
        float d0 = 0.f, d1 = 0.f, d2 = 0.f, d3 = 0.f;
        #pragma unroll 4
        for (int c = 0; c < C_; c += 4) {
            d0 += sc[c + 0] * wr[c + 0];
            d1 += sc[c + 1] * wr[c + 1];
            d2 += sc[c + 2] * wr[c + 2];
            d3 += sc[c + 3] * wr[c + 3];
        }
        o[r] = ((d0 + d1) + (d2 + d3)) + bias[v * C_ + co];
    }
    for (int n = 0; n < N_; n++) {
        long base = ((long)b * N_ + n) * (NVW * C_) + (long)v * C_;
        #pragma unroll
        for (int r = 0; r < 3; r++) out[base + t + r * 256] = o[r];
    }
}

// ---------------- launch ----------------
extern "C" void kernel_launch(void* const* d_in, const int* in_sizes, int n_in,
                              void* d_out, int out_size)
{
    const float* X        = (const float*)d_in[0];
    const float* norm1_g  = (const float*)d_in[1];
    const float* norm1_b  = (const float*)d_in[2];
    const float* qkv_w    = (const float*)d_in[3];
    const float* proj_w   = (const float*)d_in[4];
    const float* proj_b   = (const float*)d_in[5];
    const float* norm2_g  = (const float*)d_in[6];
    const float* norm2_b  = (const float*)d_in[7];
    const float* fc1_w    = (const float*)d_in[8];
    const float* fc1_b    = (const float*)d_in[9];
    const float* fc2_w    = (const float*)d_in[10];
    const float* fc2_b    = (const float*)d_in[11];
    const float* query    = (const float*)d_in[12];
    const float* mha_in_w = (const float*)d_in[13];
    const float* mha_in_b = (const float*)d_in[14];
    const float* mha_out_w= (const float*)d_in[15];
    const float* mha_out_b= (const float*)d_in[16];
    float* out = (float*)d_out;

    float *Xn, *qkvb, *ctx, *x, *hn, *h1, *x2, *kv, *qh, *c2;
    cudaGetSymbolAddress((void**)&Xn,   g_Xn);
    cudaGetSymbolAddress((void**)&qkvb, g_qkv);
    cudaGetSymbolAddress((void**)&ctx,  g_ctx);
    cudaGetSymbolAddress((void**)&x,    g_x);
    cudaGetSymbolAddress((void**)&hn,   g_hn);
    cudaGetSymbolAddress((void**)&h1,   g_h1);
    cudaGetSymbolAddress((void**)&x2,   g_x2);
    cudaGetSymbolAddress((void**)&kv,   g_kv);
    cudaGetSymbolAddress((void**)&qh,   g_qh);
    cudaGetSymbolAddress((void**)&c2,   g_c2);

    cudaFuncSetAttribute(gemm_mma, cudaFuncAttributeMaxDynamicSharedMemorySize,
                         GEMM_SMEM);

    const long MC  = (long)MROWS * C_;
    const long MH  = (long)MROWS * HID_;

    // 1. LN1 (remap [b*NV+v] -> [v][b]), shared params
    ln_kernel<<<NVW * B_ * N_, 256>>>(X, norm1_g, norm1_b, Xn, 1, 0);

    // 2. QKV GEMM: [1024,768] x [2304,768]^T -> [1024,2304]
    gemm_mma<<<dim3(3 * C_ / 128, MROWS / 128, NVW), 512, GEMM_SMEM>>>(
        Xn, qkv_w, nullptr, nullptr, qkvb,
        C_, 3 * C_, MC, (long)3 * C_ * C_, 0, 0, (long)MROWS * 3 * C_, 1.0f, 0);

    // 3. pairwise attention, mean over j
    attn_kernel<<<dim3(H_, B_, NVW), 256>>>(qkvb, ctx);

    // 4. proj GEMM, alpha=2 folds the residual doubling
    gemm_mma<<<dim3(C_ / 128, MROWS / 128, NVW), 512, GEMM_SMEM>>>(
        ctx, proj_w, proj_b, nullptr, x,
        C_, C_, MC, (long)C_ * C_, C_, 0, MC, 2.0f, 0);

    // 5. LN2 (per-view params)
    ln_kernel<<<NVW * B_ * N_, 256>>>(x, norm2_g, norm2_b, hn, 0, 1);

    // 6. fc1 GEMM + bias + GELU
    gemm_mma<<<dim3(HID_ / 128, MROWS / 128, NVW), 512, GEMM_SMEM>>>(
        hn, fc1_w, fc1_b, nullptr, h1,
        C_, HID_, MC, (long)HID_ * C_, HID_, 0, MH, 1.0f, 1);

    // 7. fc2 GEMM + bias + residual add (x)
    gemm_mma<<<dim3(C_ / 128, MROWS / 128, NVW), 512, GEMM_SMEM>>>(
        h1, fc2_w, fc2_b, x, x2,
        HID_, C_, MH, (long)C_ * HID_, C_, MC, MC, 1.0f, 0);

    // 8. learnable query projection
    qh_kernel<<<NVW, 256>>>(query, mha_in_w, mha_in_b, qh);

    // 9. K/V projection of x2
    gemm_mma<<<dim3(2 * C_ / 128, MROWS / 128, NVW), 512, GEMM_SMEM>>>(
        x2, mha_in_w + (long)C_ * C_, mha_in_b + C_, nullptr, kv,
        C_, 2 * C_, MC, (long)3 * C_ * C_, (long)3 * C_, 0, (long)MROWS * 2 * C_, 1.0f, 0);

    // 10. single-query cross attention -> c2[v][b][C]
    cross_attn_kernel<<<dim3(H_, B_, NVW), 256>>>(kv, qh, c2);

    // 11. output projection + broadcast over N
    out_kernel<<<dim3(NVW, B_), 256>>>(c2, mha_out_w, mha_out_b, out);
}

// round 8
// speedup vs baseline: 1.0009x; 1.0009x over previous
#include <cuda_runtime.h>
#include <math.h>
#include <stdint.h>

#define NVW 4
#define B_ 4
#define N_ 256
#define C_ 768
#define H_ 12
#define HD_ 64
#define HID_ 3072
#define MROWS (B_*N_)   // 1024 rows per view

// ---------------- scratch (device globals; no allocation) ----------------
__device__ float g_Xn [NVW*MROWS*C_];
__device__ float g_qkv[NVW*MROWS*3*C_];
__device__ float g_ctx[NVW*MROWS*C_];
__device__ float g_x  [NVW*MROWS*C_];
__device__ float g_hn [NVW*MROWS*C_];
__device__ float g_h1 [NVW*MROWS*HID_];
__device__ float g_x2 [NVW*MROWS*C_];
__device__ float g_kv [NVW*MROWS*2*C_];
__device__ float g_qh [NVW*C_];
__device__ float g_c2 [NVW*B_*C_];

__device__ __forceinline__ float gelu_exact(float x) {
    return 0.5f * x * (1.0f + erff(x * 0.70710678118654752f));
}

__device__ __forceinline__ float to_tf32(float x) {
    float r;
    asm("cvt.rna.tf32.f32 %0, %1;" : "=f"(r) : "f"(x));
    return r;
}

#define MMA_TF32(d, a, b) \
    asm volatile( \
        "mma.sync.aligned.m16n8k8.row.col.f32.tf32.tf32.f32 " \
        "{%0,%1,%2,%3}, {%4,%5,%6,%7}, {%8,%9}, {%0,%1,%2,%3};" \
        : "+f"((d)[0]), "+f"((d)[1]), "+f"((d)[2]), "+f"((d)[3]) \
        : "r"((a)[0]), "r"((a)[1]), "r"((a)[2]), "r"((a)[3]), \
          "r"((b)[0]), "r"((b)[1]))

// ---------------- LayerNorm ----------------
__global__ __launch_bounds__(256) void ln_kernel(
    const float* __restrict__ X, const float* __restrict__ g,
    const float* __restrict__ be, float* __restrict__ Y,
    int remap, int pervw)
{
    int r = blockIdx.x;
    int v = r / (B_ * N_);
    long inrow;
    if (remap) {
        int rem = r % (B_ * N_);
        int bb = rem / N_;
        int n  = rem % N_;
        inrow = ((long)(bb * NVW + v) * N_ + n);
    } else {
        inrow = r;
    }
    const float* x = X + inrow * C_;
    float* y = Y + (long)r * C_;
    const float* gg = g  + (pervw ? v * C_ : 0);
    const float* bb2 = be + (pervw ? v * C_ : 0);

    int t = threadIdx.x;
    float v0 = x[t], v1 = x[t + 256], v2 = x[t + 512];
    float s  = v0 + v1 + v2;
    float sq = v0 * v0 + v1 * v1 + v2 * v2;

    __shared__ float rs[256], rq[256];
    rs[t] = s; rq[t] = sq;
    __syncthreads();
    for (int off = 128; off > 0; off >>= 1) {
        if (t < off) { rs[t] += rs[t + off]; rq[t] += rq[t + off]; }
        __syncthreads();
    }
    float mean = rs[0] * (1.0f / C_);
    float var  = rq[0] * (1.0f / C_) - mean * mean;
    float rstd = rsqrtf(var + 1e-6f);

    y[t]       = (v0 - mean) * rstd * gg[t]       + bb2[t];
    y[t + 256] = (v1 - mean) * rstd * gg[t + 256] + bb2[t + 256];
    y[t + 512] = (v2 - mean) * rstd * gg[t + 512] + bb2[t + 512];
}

// ---------------- 3xTF32 mma.sync batched NT GEMM (v3) ----------------
// CTA tile 128x128, 512 threads, 16 warps (4x4), warp tile 32x32.
// hi/lo precomputed at staging into 4 smem tiles [k][row] stride 136.
// Per kk: issue all hi*hi MMAs (8 indep acc), then hi*lo, then lo*hi —
// accumulator reuse spaced 8 MMAs apart so RAW latency is hidden.
#define KC 32
#define SROW 136
#define TILE_F (KC * SROW)                  // 4352 floats per tile
#define GEMM_SMEM (2 * 4 * TILE_F * 4)      // 139264 bytes

__global__ void __launch_bounds__(512, 1)
gemm_mma(const float* __restrict__ A, const float* __restrict__ W,
         const float* __restrict__ bias, const float* __restrict__ res,
         float* __restrict__ Cout, int Kdim, int D,
         long sA, long sW, long sB, long sR, long sC, float alpha, int act)
{
    extern __shared__ float sm[];
    const int v = blockIdx.z;
    const float* Av = A + (long)v * sA;
    const float* Wv = W + (long)v * sW;
    float* Cv = Cout + (long)v * sC;
    const int bm = blockIdx.y * 128, bn = blockIdx.x * 128;

    const int t = threadIdx.x, lane = t & 31, wid = t >> 5;
    const int wm = (wid >> 2) * 32;
    const int wn = (wid & 3) * 32;

    const int srow = t & 127;
    const int k4b = t >> 7;

    const int fr = lane >> 2;
    const int fk = lane & 3;

    float acc[2][4][4];
    #pragma unroll
    for (int a = 0; a < 2; a++)
        #pragma unroll
        for (int b = 0; b < 4; b++)
            #pragma unroll
            for (int c = 0; c < 4; c++) acc[a][b][c] = 0.0f;

    float4 aR[2], wR[2];
    const int steps = Kdim / KC;

    // ---- preload + stage chunk 0 ----
    {
        const float* Ap = Av + (long)(bm + srow) * Kdim;
        const float* Wp = Wv + (long)(bn + srow) * Kdim;
        #pragma unroll
        for (int s = 0; s < 2; s++) {
            int k4 = k4b + 4 * s;
            aR[s] = *(const float4*)(Ap + k4 * 4);
            wR[s] = *(const float4*)(Wp + k4 * 4);
        }
        float* Ahi = sm;
        float* Alo = Ahi + TILE_F;
        float* Whi = Alo + TILE_F;
        float* Wlo = Whi + TILE_F;
        #pragma unroll
        for (int s = 0; s < 2; s++) {
            int k = (k4b + 4 * s) * 4;
            float av[4] = {aR[s].x, aR[s].y, aR[s].z, aR[s].w};
            float wv[4] = {wR[s].x, wR[s].y, wR[s].z, wR[s].w};
            #pragma unroll
            for (int i = 0; i < 4; i++) {
                float ah = to_tf32(av[i]);
                float wh = to_tf32(wv[i]);
                Ahi[(k + i) * SROW + srow] = ah;
                Alo[(k + i) * SROW + srow] = to_tf32(av[i] - ah);
                Whi[(k + i) * SROW + srow] = wh;
                Wlo[(k + i) * SROW + srow] = to_tf32(wv[i] - wh);
            }
        }
    }
    __syncthreads();

    for (int c = 0; c < steps; c++) {
        bool more = (c + 1 < steps);
        if (more) {
            const float* Ap = Av + (long)(bm + srow) * Kdim + (c + 1) * KC;
            const float* Wp = Wv + (long)(bn + srow) * Kdim + (c + 1) * KC;
            #pragma unroll
            for (int s = 0; s < 2; s++) {
                int k4 = k4b + 4 * s;
                aR[s] = *(const float4*)(Ap + k4 * 4);
                wR[s] = *(const float4*)(Wp + k4 * 4);
            }
        }

        const float* Ahi = sm + (c & 1) * 4 * TILE_F;
        const float* Alo = Ahi + TILE_F;
        const float* Whi = Alo + TILE_F;
        const float* Wlo = Whi + TILE_F;

        #pragma unroll
        for (int kk = 0; kk < 4; kk++) {
            int k0 = kk * 8 + fk;
            uint32_t ah[2][4], al[2][4], bh[4][2], bl[4][2];
            #pragma unroll
            for (int mt = 0; mt < 2; mt++) {
                int r0 = wm + mt * 16 + fr;
                ah[mt][0] = __float_as_uint(Ahi[(k0    ) * SROW + r0]);
                ah[mt][1] = __float_as_uint(Ahi[(k0    ) * SROW + r0 + 8]);
                ah[mt][2] = __float_as_uint(Ahi[(k0 + 4) * SROW + r0]);
                ah[mt][3] = __float_as_uint(Ahi[(k0 + 4) * SROW + r0 + 8]);
                al[mt][0] = __float_as_uint(Alo[(k0    ) * SROW + r0]);
                al[mt][1] = __float_as_uint(Alo[(k0    ) * SROW + r0 + 8]);
                al[mt][2] = __float_as_uint(Alo[(k0 + 4) * SROW + r0]);
                al[mt][3] = __float_as_uint(Alo[(k0 + 4) * SROW + r0 + 8]);
            }
            #pragma unroll
            for (int nt = 0; nt < 4; nt++) {
                int n0 = wn + nt * 8 + fr;
                bh[nt][0] = __float_as_uint(Whi[(k0    ) * SROW + n0]);
                bh[nt][1] = __float_as_uint(Whi[(k0 + 4) * SROW + n0]);
                bl[nt][0] = __float_as_uint(Wlo[(k0    ) * SROW + n0]);
                bl[nt][1] = __float_as_uint(Wlo[(k0 + 4) * SROW + n0]);
            }
            // term-major ordering: 8 independent accumulators between
            // any two MMAs that share an accumulator (RAW latency hidden)
            #pragma unroll
            for (int mt = 0; mt < 2; mt++)
                #pragma unroll
                for (int nt = 0; nt < 4; nt++)
                    MMA_TF32(acc[mt][nt], ah[mt], bh[nt]);
            #pragma unroll
            for (int mt = 0; mt < 2; mt++)
                #pragma unroll
                for (int nt = 0; nt < 4; nt++)
                    MMA_TF32(acc[mt][nt], ah[mt], bl[nt]);
            #pragma unroll
            for (int mt = 0; mt < 2; mt++)
                #pragma unroll
                for (int nt = 0; nt < 4; nt++)
                    MMA_TF32(acc[mt][nt], al[mt], bh[nt]);
        }

        if (more) {
            float* Ahi2 = sm + ((c + 1) & 1) * 4 * TILE_F;
            float* Alo2 = Ahi2 + TILE_F;
            float* Whi2 = Alo2 + TILE_F;
            float* Wlo2 = Whi2 + TILE_F;
            #pragma unroll
            for (int s = 0; s < 2; s++) {
                int k = (k4b + 4 * s) * 4;
                float av[4] = {aR[s].x, aR[s].y, aR[s].z, aR[s].w};
                float wv[4] = {wR[s].x, wR[s].y, wR[s].z, wR[s].w};
                #pragma unroll
                for (int i = 0; i < 4; i++) {
                    float ahh = to_tf32(av[i]);
                    float whh = to_tf32(wv[i]);
                    Ahi2[(k + i) * SROW + srow] = ahh;
                    Alo2[(k + i) * SROW + srow] = to_tf32(av[i] - ahh);
                    Whi2[(k + i) * SROW + srow] = whh;
                    Wlo2[(k + i) * SROW + srow] = to_tf32(wv[i] - whh);
                }
            }
        }
        __syncthreads();
    }

    // epilogue
    #pragma unroll
    for (int mt = 0; mt < 2; mt++) {
        #pragma unroll
        for (int nt = 0; nt < 4; nt++) {
            int row = bm + wm + mt * 16 + fr;
            int col = bn + wn + nt * 8 + 2 * fk;
            float b0 = 0.f, b1 = 0.f;
            if (bias) {
                b0 = bias[(long)v * sB + col];
                b1 = bias[(long)v * sB + col + 1];
            }
            #pragma unroll
            for (int half = 0; half < 2; half++) {
                int r = row + half * 8;
                float v0 = alpha * (acc[mt][nt][half * 2 + 0] + b0);
                float v1 = alpha * (acc[mt][nt][half * 2 + 1] + b1);
                if (act == 1) { v0 = gelu_exact(v0); v1 = gelu_exact(v1); }
                if (res) {
                    v0 += res[(long)v * sR + (long)r * D + col];
                    v1 += res[(long)v * sR + (long)r * D + col + 1];
                }
                float2 o2 = {v0, v1};
                *(float2*)&Cv[(long)r * D + col] = o2;
            }
        }
    }
}

// ---------------- Pairwise cross-view attention with mean over j ----------------
__global__ __launch_bounds__(256) void attn_kernel(
    const float* __restrict__ qkv, float* __restrict__ ctx_out)
{
    int h = blockIdx.x, b = blockIdx.y, i = blockIdx.z;
    int n = threadIdx.x;
    const float scale = 0.125f;

    __shared__ __align__(16) float sKV[64 * 64];

    float q[64];
    const float* qptr = qkv + ((long)((i * B_ + b) * N_ + n)) * (3 * C_) + h * HD_;
    #pragma unroll
    for (int e4 = 0; e4 < 16; e4++) {
        float4 t4 = *(const float4*)(qptr + e4 * 4);
        q[e4 * 4 + 0] = t4.x; q[e4 * 4 + 1] = t4.y;
        q[e4 * 4 + 2] = t4.z; q[e4 * 4 + 3] = t4.w;
    }

    float ctx[64];
    #pragma unroll
    for (int e = 0; e < 64; e++) ctx[e] = 0.0f;

    float sloc[256];

    for (int j = 0; j < NVW; j++) {
        const float* kbase = qkv + ((long)((j * B_ + b) * N_)) * (3 * C_) + C_ + h * HD_;
        const float* vbase = kbase + C_;

        float smax = -1e30f;
        for (int c = 0; c < 4; c++) {
            __syncthreads();
            #pragma unroll
            for (int r = 0; r < 4; r++) {
                int F = threadIdx.x + 256 * r;
                int row  = F >> 4;
                int col4 = (F & 15) << 2;
                float4 t4 = *(const float4*)(kbase + (long)(c * 64 + row) * (3 * C_) + col4);
                *(float4*)&sKV[row * 64 + col4] = t4;
            }
            __syncthreads();
            for (int m = 0; m < 64; m++) {
                float d0 = 0.f, d1 = 0.f, d2 = 0.f, d3 = 0.f;
                const float* kr = &sKV[m * 64];
                #pragma unroll
                for (int e = 0; e < 64; e += 4) {
                    d0 += q[e + 0] * kr[e + 0];
                    d1 += q[e + 1] * kr[e + 1];
                    d2 += q[e + 2] * kr[e + 2];
                    d3 += q[e + 3] * kr[e + 3];
                }
                float s = ((d0 + d1) + (d2 + d3)) * scale;
                sloc[c * 64 + m] = s;
                smax = fmaxf(smax, s);
            }
        }
        float ssum = 0.0f;
        for (int m = 0; m < 256; m++) {
            float e_ = __expf(sloc[m] - smax);
            sloc[m] = e_;
            ssum += e_;
        }
        float inv = 1.0f / ssum;

        for (int c = 0; c < 4; c++) {
            __syncthreads();
            #pragma unroll
            for (int r = 0; r < 4; r++) {
                int F = threadIdx.x + 256 * r;
                int row  = F >> 4;
                int col4 = (F & 15) << 2;
                float4 t4 = *(const float4*)(vbase + (long)(c * 64 + row) * (3 * C_) + col4);
                *(float4*)&sKV[row * 64 + col4] = t4;
            }
            __syncthreads();
            for (int m = 0; m < 64; m++) {
                float pm = sloc[c * 64 + m] * inv;
                const float* vr = &sKV[m * 64];
                #pragma unroll
                for (int e = 0; e < 64; e++) ctx[e] += pm * vr[e];
            }
        }
    }

    float* outp = ctx_out + ((long)((i * B_ + b) * N_ + n)) * C_ + h * HD_;
    #pragma unroll
    for (int e4 = 0; e4 < 16; e4++) {
        float4 o4;
        o4.x = ctx[e4 * 4 + 0] * 0.25f;
        o4.y = ctx[e4 * 4 + 1] * 0.25f;
        o4.z = ctx[e4 * 4 + 2] * 0.25f;
        o4.w = ctx[e4 * 4 + 3] * 0.25f;
        *(float4*)(outp + e4 * 4) = o4;
    }
}

// ---------------- learnable-query projection ----------------
__global__ __launch_bounds__(256) void qh_kernel(
    const float* __restrict__ query, const float* __restrict__ w,
    const float* __restrict__ bq, float* __restrict__ qh)
{
    int v = blockIdx.x;
    int t = threadIdx.x;
    for (int d = t; d < C_; d += 256) {
        const float* wr = w + (long)v * (3 * C_) * C_ + (long)d * C_;
        float acc = 0.0f;
        #pragma unroll 4
        for (int c = 0; c < C_; c++) acc += query[c] * wr[c];
        qh[v * C_ + d] = acc + bq[(long)v * (3 * C_) + d];
    }
}

// ---------------- cross attention (single query) ----------------
__global__ __launch_bounds__(256) void cross_attn_kernel(
    const float* __restrict__ kv, const float* __restrict__ qh,
    float* __restrict__ c2)
{
    int h = blockIdx.x, b = blockIdx.y, v = blockIdx.z;
    int t = threadIdx.x;

    __shared__ float p[256];
    __shared__ float red[256];
    __shared__ float part[4][64];

    const float* kvb = kv + ((long)(v * B_ + b) * N_) * (2 * C_);
    const float* qhp = qh + v * C_ + h * HD_;
    const float* krow = kvb + (long)t * (2 * C_) + h * HD_;

    float s = 0.0f;
    #pragma unroll
    for (int e = 0; e < 64; e++) s += qhp[e] * krow[e];
    s *= 0.125f;

    red[t] = s; __syncthreads();
    for (int off = 128; off > 0; off >>= 1) {
        if (t < off) red[t] = fmaxf(red[t], red[t + off]);
        __syncthreads();
    }
    float mx = red[0];
    __syncthreads();

    float e_ = __expf(s - mx);
    p[t] = e_; red[t] = e_;
    __syncthreads();
    for (int off = 128; off > 0; off >>= 1) {
        if (t < off) red[t] += red[t + off];
        __syncthreads();
    }
    float inv = 1.0f / red[0];
    __syncthreads();

    int e = t & 63, pid = t >> 6;
    float acc = 0.0f;
    for (int n = pid * 64; n < pid * 64 + 64; n++)
        acc += p[n] * kvb[(long)n * (2 * C_) + C_ + h * HD_ + e];
    part[pid][e] = acc;
    __syncthreads();
    if (t < 64) {
        float r = (part[0][t] + part[1][t]) + (part[2][t] + part[3][t]);
        c2[(long)(v * B_ + b) * C_ + h * HD_ + t] = r * inv;
    }
}

// ---------------- output projection + broadcast over N ----------------
__global__ __launch_bounds__(256) void out_kernel(
    const float* __restrict__ c2, const float* __restrict__ w,
    const float* __restrict__ bias, float* __restrict__ out)
{
    int v = blockIdx.x, b = blockIdx.y;
    int t = threadIdx.x;

    __shared__ float sc[C_];
    for (int c = t; c < C_; c += 256) sc[c] = c2[(long)(v * B_ + b) * C_ + c];
    __syncthreads();

    float o[3];
    #pragma unroll
    for (int r = 0; r < 3; r++) {
        int co = t + r * 256;
        const float* wr = w + (long)v * C_ * C_ + (long)co * C_;
        float d0 = 0.f, d1 = 0.f, d2 = 0.f, d3 = 0.f;
        #pragma unroll 4
        for (int c = 0; c < C_; c += 4) {
            d0 += sc[c + 0] * wr[c + 0];
            d1 += sc[c + 1] * wr[c + 1];
            d2 += sc[c + 2] * wr[c + 2];
            d3 += sc[c + 3] * wr[c + 3];
        }
        o[r] = ((d0 + d1) + (d2 + d3)) + bias[v * C_ + co];
    }
    for (int n = 0; n < N_; n++) {
        long base = ((long)b * N_ + n) * (NVW * C_) + (long)v * C_;
        #pragma unroll
        for (int r = 0; r < 3; r++) out[base + t + r * 256] = o[r];
    }
}

// ---------------- launch ----------------
extern "C" void kernel_launch(void* const* d_in, const int* in_sizes, int n_in,
                              void* d_out, int out_size)
{
    const float* X        = (const float*)d_in[0];
    const float* norm1_g  = (const float*)d_in[1];
    const float* norm1_b  = (const float*)d_in[2];
    const float* qkv_w    = (const float*)d_in[3];
    const float* proj_w   = (const float*)d_in[4];
    const float* proj_b   = (const float*)d_in[5];
    const float* norm2_g  = (const float*)d_in[6];
    const float* norm2_b  = (const float*)d_in[7];
    const float* fc1_w    = (const float*)d_in[8];
    const float* fc1_b    = (const float*)d_in[9];
    const float* fc2_w    = (const float*)d_in[10];
    const float* fc2_b    = (const float*)d_in[11];
    const float* query    = (const float*)d_in[12];
    const float* mha_in_w = (const float*)d_in[13];
    const float* mha_in_b = (const float*)d_in[14];
    const float* mha_out_w= (const float*)d_in[15];
    const float* mha_out_b= (const float*)d_in[16];
    float* out = (float*)d_out;

    float *Xn, *qkvb, *ctx, *x, *hn, *h1, *x2, *kv, *qh, *c2;
    cudaGetSymbolAddress((void**)&Xn,   g_Xn);
    cudaGetSymbolAddress((void**)&qkvb, g_qkv);
    cudaGetSymbolAddress((void**)&ctx,  g_ctx);
    cudaGetSymbolAddress((void**)&x,    g_x);
    cudaGetSymbolAddress((void**)&hn,   g_hn);
    cudaGetSymbolAddress((void**)&h1,   g_h1);
    cudaGetSymbolAddress((void**)&x2,   g_x2);
    cudaGetSymbolAddress((void**)&kv,   g_kv);
    cudaGetSymbolAddress((void**)&qh,   g_qh);
    cudaGetSymbolAddress((void**)&c2,   g_c2);

    cudaFuncSetAttribute(gemm_mma, cudaFuncAttributeMaxDynamicSharedMemorySize,
                         GEMM_SMEM);

    const long MC  = (long)MROWS * C_;
    const long MH  = (long)MROWS * HID_;

    // 1. LN1 (remap [b*NV+v] -> [v][b]), shared params
    ln_kernel<<<NVW * B_ * N_, 256>>>(X, norm1_g, norm1_b, Xn, 1, 0);

    // 2. QKV GEMM: [1024,768] x [2304,768]^T -> [1024,2304]
    gemm_mma<<<dim3(3 * C_ / 128, MROWS / 128, NVW), 512, GEMM_SMEM>>>(
        Xn, qkv_w, nullptr, nullptr, qkvb,
        C_, 3 * C_, MC, (long)3 * C_ * C_, 0, 0, (long)MROWS * 3 * C_, 1.0f, 0);

    // 3. pairwise attention, mean over j
    attn_kernel<<<dim3(H_, B_, NVW), 256>>>(qkvb, ctx);

    // 4. proj GEMM, alpha=2 folds the residual doubling
    gemm_mma<<<dim3(C_ / 128, MROWS / 128, NVW), 512, GEMM_SMEM>>>(
        ctx, proj_w, proj_b, nullptr, x,
        C_, C_, MC, (long)C_ * C_, C_, 0, MC, 2.0f, 0);

    // 5. LN2 (per-view params)
    ln_kernel<<<NVW * B_ * N_, 256>>>(x, norm2_g, norm2_b, hn, 0, 1);

    // 6. fc1 GEMM + bias + GELU
    gemm_mma<<<dim3(HID_ / 128, MROWS / 128, NVW), 512, GEMM_SMEM>>>(
        hn, fc1_w, fc1_b, nullptr, h1,
        C_, HID_, MC, (long)HID_ * C_, HID_, 0, MH, 1.0f, 1);

    // 7. fc2 GEMM + bias + residual add (x)
    gemm_mma<<<dim3(C_ / 128, MROWS / 128, NVW), 512, GEMM_SMEM>>>(
        h1, fc2_w, fc2_b, x, x2,
        HID_, C_, MH, (long)C_ * HID_, C_, MC, MC, 1.0f, 0);

    // 8. learnable query projection
    qh_kernel<<<NVW, 256>>>(query, mha_in_w, mha_in_b, qh);

    // 9. K/V projection of x2
    gemm_mma<<<dim3(2 * C_ / 128, MROWS / 128, NVW), 512, GEMM_SMEM>>>(
        x2, mha_in_w + (long)C_ * C_, mha_in_b + C_, nullptr, kv,
        C_, 2 * C_, MC, (long)3 * C_ * C_, (long)3 * C_, 0, (long)MROWS * 2 * C_, 1.0f, 0);

    // 10. single-query cross attention -> c2[v][b][C]
    cross_attn_kernel<<<dim3(H_, B_, NVW), 256>>>(kv, qh, c2);

    // 11. output projection + broadcast over N
    out_kernel<<<dim3(NVW, B_), 256>>>(c2, mha_out_w, mha_out_b, out);
}

// round 9
// speedup vs baseline: 1.0565x; 1.0556x over previous
#include <cuda_runtime.h>
#include <math.h>
#include <stdint.h>

#define NVW 4
#define B_ 4
#define N_ 256
#define C_ 768
#define H_ 12
#define HD_ 64
#define HID_ 3072
#define MROWS (B_*N_)   // 1024 rows per view

// ---------------- scratch (device globals; no allocation) ----------------
__device__ float g_Xn [NVW*MROWS*C_];
__device__ float g_qkv[NVW*MROWS*3*C_];
__device__ float g_ctx[NVW*MROWS*C_];
__device__ float g_x  [NVW*MROWS*C_];
__device__ float g_hn [NVW*MROWS*C_];
__device__ float g_h1 [NVW*MROWS*HID_];
__device__ float g_x2 [NVW*MROWS*C_];
__device__ float g_kv [NVW*MROWS*2*C_];
__device__ float g_qh [NVW*C_];
__device__ float g_c2 [NVW*B_*C_];

__device__ __forceinline__ float gelu_exact(float x) {
    return 0.5f * x * (1.0f + erff(x * 0.70710678118654752f));
}

__device__ __forceinline__ float to_tf32(float x) {
    float r;
    asm("cvt.rna.tf32.f32 %0, %1;" : "=f"(r) : "f"(x));
    return r;
}

__device__ __forceinline__ uint32_t smem_u32(const void* p) {
    uint32_t a;
    asm("{ .reg .u64 t; cvta.to.shared.u64 t, %1; cvt.u32.u64 %0, t; }"
        : "=r"(a) : "l"(p));
    return a;
}

#define CP_ASYNC16(dst, src) \
    asm volatile("cp.async.ca.shared.global [%0], [%1], 16;" \
                 :: "r"(dst), "l"(src) : "memory")
#define CP_COMMIT() \
    asm volatile("cp.async.commit_group;" ::: "memory")
#define CP_WAIT2() \
    asm volatile("cp.async.wait_group 2;" ::: "memory")

#define MMA_TF32(d, a, b) \
    asm volatile( \
        "mma.sync.aligned.m16n8k8.row.col.f32.tf32.tf32.f32 " \
        "{%0,%1,%2,%3}, {%4,%5,%6,%7}, {%8,%9}, {%0,%1,%2,%3};" \
        : "+f"((d)[0]), "+f"((d)[1]), "+f"((d)[2]), "+f"((d)[3]) \
        : "r"((a)[0]), "r"((a)[1]), "r"((a)[2]), "r"((a)[3]), \
          "r"((b)[0]), "r"((b)[1]))

// ---------------- LayerNorm ----------------
__global__ __launch_bounds__(256) void ln_kernel(
    const float* __restrict__ X, const float* __restrict__ g,
    const float* __restrict__ be, float* __restrict__ Y,
    int remap, int pervw)
{
    int r = blockIdx.x;
    int v = r / (B_ * N_);
    long inrow;
    if (remap) {
        int rem = r % (B_ * N_);
        int bb = rem / N_;
        int n  = rem % N_;
        inrow = ((long)(bb * NVW + v) * N_ + n);
    } else {
        inrow = r;
    }
    const float* x = X + inrow * C_;
    float* y = Y + (long)r * C_;
    const float* gg = g  + (pervw ? v * C_ : 0);
    const float* bb2 = be + (pervw ? v * C_ : 0);

    int t = threadIdx.x;
    float v0 = x[t], v1 = x[t + 256], v2 = x[t + 512];
    float s  = v0 + v1 + v2;
    float sq = v0 * v0 + v1 * v1 + v2 * v2;

    __shared__ float rs[256], rq[256];
    rs[t] = s; rq[t] = sq;
    __syncthreads();
    for (int off = 128; off > 0; off >>= 1) {
        if (t < off) { rs[t] += rs[t + off]; rq[t] += rq[t + off]; }
        __syncthreads();
    }
    float mean = rs[0] * (1.0f / C_);
    float var  = rq[0] * (1.0f / C_) - mean * mean;
    float rstd = rsqrtf(var + 1e-6f);

    y[t]       = (v0 - mean) * rstd * gg[t]       + bb2[t];
    y[t + 256] = (v1 - mean) * rstd * gg[t + 256] + bb2[t + 256];
    y[t + 512] = (v2 - mean) * rstd * gg[t + 512] + bb2[t + 512];
}

// ---------------- 3xTF32 mma.sync batched NT GEMM (v4: cp.async pipeline) ----
// CTA tile 128x128, 256 threads, 8 warps (2x4), warp tile 64x32.
// Raw fp32 tiles staged via 4-stage cp.async ([row][k] stride 36, conflict-free
// fragment reads: bank = 4*fr+fk). hi/lo tf32 split at fragment-load time.
// One __syncthreads per K-chunk of 32; 3 chunks always in flight.
#define KC 32
#define RSTRIDE 36
#define TILE_F (128 * RSTRIDE)              // 4608 floats
#define NSTAGE 4
#define GEMM_SMEM (NSTAGE * 2 * TILE_F * 4) // 147456 bytes

__global__ void __launch_bounds__(256, 1)
gemm_mma(const float* __restrict__ A, const float* __restrict__ W,
         const float* __restrict__ bias, const float* __restrict__ res,
         float* __restrict__ Cout, int Kdim, int D,
         long sA, long sW, long sB, long sR, long sC, float alpha, int act)
{
    extern __shared__ float sm[];
    const int v = blockIdx.z;
    const float* Av = A + (long)v * sA;
    const float* Wv = W + (long)v * sW;
    float* Cv = Cout + (long)v * sC;
    const int bm = blockIdx.y * 128, bn = blockIdx.x * 128;

    const int t = threadIdx.x, lane = t & 31, wid = t >> 5;
    const int wm = (wid >> 2) * 64;    // 2 row groups
    const int wn = (wid & 3) * 32;     // 4 col groups

    const int fr = lane >> 2;          // 0..7
    const int fk = lane & 3;           // 0..3

    // cp.async mapping: thread handles one row of one tile (A or W), 8x16B
    const int crow  = t & 127;
    const int ctile = t >> 7;          // 0 = A, 1 = W
    const float* gsrc = (ctile ? (Wv + (long)(bn + crow) * Kdim)
                               : (Av + (long)(bm + crow) * Kdim));
    const uint32_t sbase = smem_u32(sm);
    const uint32_t srowoff = (uint32_t)((ctile * TILE_F + crow * RSTRIDE) * 4);

    float acc[4][4][4];
    #pragma unroll
    for (int a = 0; a < 4; a++)
        #pragma unroll
        for (int b = 0; b < 4; b++)
            #pragma unroll
            for (int c = 0; c < 4; c++) acc[a][b][c] = 0.0f;

    const int steps = Kdim / KC;

    // prologue: stages 0,1,2
    #pragma unroll
    for (int p = 0; p < 3; p++) {
        if (p < steps) {
            uint32_t dst = sbase + (uint32_t)((p & 3) * 2 * TILE_F * 4) + srowoff;
            const float* g = gsrc + p * KC;
            #pragma unroll
            for (int i = 0; i < 8; i++)
                CP_ASYNC16(dst + i * 16, g + i * 4);
        }
        CP_COMMIT();
    }

    for (int c = 0; c < steps; c++) {
        CP_WAIT2();
        __syncthreads();

        // issue chunk c+3 (buffer (c+3)&3 = (c-1)&3, reads finished pre-sync)
        {
            int p = c + 3;
            if (p < steps) {
                uint32_t dst = sbase + (uint32_t)((p & 3) * 2 * TILE_F * 4) + srowoff;
                const float* g = gsrc + p * KC;
                #pragma unroll
                for (int i = 0; i < 8; i++)
                    CP_ASYNC16(dst + i * 16, g + i * 4);
            }
            CP_COMMIT();
        }

        const float* As = sm + (c & 3) * 2 * TILE_F;
        const float* Ws = As + TILE_F;

        #pragma unroll
        for (int kk = 0; kk < 4; kk++) {
            int k0 = kk * 8 + fk;
            uint32_t ah[4][4], al[4][4], bh[4][2], bl[4][2];
            #pragma unroll
            for (int mt = 0; mt < 4; mt++) {
                int r0 = wm + mt * 16 + fr;
                float f0 = As[(r0    ) * RSTRIDE + k0];
                float f1 = As[(r0 + 8) * RSTRIDE + k0];
                float f2 = As[(r0    ) * RSTRIDE + k0 + 4];
                float f3 = As[(r0 + 8) * RSTRIDE + k0 + 4];
                float h0 = to_tf32(f0), h1 = to_tf32(f1);
                float h2 = to_tf32(f2), h3 = to_tf32(f3);
                ah[mt][0] = __float_as_uint(h0);
                ah[mt][1] = __float_as_uint(h1);
                ah[mt][2] = __float_as_uint(h2);
                ah[mt][3] = __float_as_uint(h3);
                al[mt][0] = __float_as_uint(to_tf32(f0 - h0));
                al[mt][1] = __float_as_uint(to_tf32(f1 - h1));
                al[mt][2] = __float_as_uint(to_tf32(f2 - h2));
                al[mt][3] = __float_as_uint(to_tf32(f3 - h3));
            }
            #pragma unroll
            for (int nt = 0; nt < 4; nt++) {
                int n0 = wn + nt * 8 + fr;
                float f0 = Ws[n0 * RSTRIDE + k0];
                float f1 = Ws[n0 * RSTRIDE + k0 + 4];
                float h0 = to_tf32(f0), h1 = to_tf32(f1);
                bh[nt][0] = __float_as_uint(h0);
                bh[nt][1] = __float_as_uint(h1);
                bl[nt][0] = __float_as_uint(to_tf32(f0 - h0));
                bl[nt][1] = __float_as_uint(to_tf32(f1 - h1));
            }
            #pragma unroll
            for (int mt = 0; mt < 4; mt++)
                #pragma unroll
                for (int nt = 0; nt < 4; nt++) {
                    MMA_TF32(acc[mt][nt], ah[mt], bh[nt]);
                    MMA_TF32(acc[mt][nt], ah[mt], bl[nt]);
                    MMA_TF32(acc[mt][nt], al[mt], bh[nt]);
                }
        }
        __syncthreads();
    }

    // epilogue
    #pragma unroll
    for (int mt = 0; mt < 4; mt++) {
        #pragma unroll
        for (int nt = 0; nt < 4; nt++) {
            int row = bm + wm + mt * 16 + fr;
            int col = bn + wn + nt * 8 + 2 * fk;
            float b0 = 0.f, b1 = 0.f;
            if (bias) {
                b0 = bias[(long)v * sB + col];
                b1 = bias[(long)v * sB + col + 1];
            }
            #pragma unroll
            for (int half = 0; half < 2; half++) {
                int r = row + half * 8;
                float v0 = alpha * (acc[mt][nt][half * 2 + 0] + b0);
                float v1 = alpha * (acc[mt][nt][half * 2 + 1] + b1);
                if (act == 1) { v0 = gelu_exact(v0); v1 = gelu_exact(v1); }
                if (res) {
                    v0 += res[(long)v * sR + (long)r * D + col];
                    v1 += res[(long)v * sR + (long)r * D + col + 1];
                }
                float2 o2 = {v0, v1};
                *(float2*)&Cv[(long)r * D + col] = o2;
            }
        }
    }
}

// ---------------- Pairwise cross-view attention with mean over j ----------------
__global__ __launch_bounds__(256) void attn_kernel(
    const float* __restrict__ qkv, float* __restrict__ ctx_out)
{
    int h = blockIdx.x, b = blockIdx.y, i = blockIdx.z;
    int n = threadIdx.x;
    const float scale = 0.125f;

    __shared__ __align__(16) float sKV[64 * 64];

    float q[64];
    const float* qptr = qkv + ((long)((i * B_ + b) * N_ + n)) * (3 * C_) + h * HD_;
    #pragma unroll
    for (int e4 = 0; e4 < 16; e4++) {
        float4 t4 = *(const float4*)(qptr + e4 * 4);
        q[e4 * 4 + 0] = t4.x; q[e4 * 4 + 1] = t4.y;
        q[e4 * 4 + 2] = t4.z; q[e4 * 4 + 3] = t4.w;
    }

    float ctx[64];
    #pragma unroll
    for (int e = 0; e < 64; e++) ctx[e] = 0.0f;

    float sloc[256];

    for (int j = 0; j < NVW; j++) {
        const float* kbase = qkv + ((long)((j * B_ + b) * N_)) * (3 * C_) + C_ + h * HD_;
        const float* vbase = kbase + C_;

        float smax = -1e30f;
        for (int c = 0; c < 4; c++) {
            __syncthreads();
            #pragma unroll
            for (int r = 0; r < 4; r++) {
                int F = threadIdx.x + 256 * r;
                int row  = F >> 4;
                int col4 = (F & 15) << 2;
                float4 t4 = *(const float4*)(kbase + (long)(c * 64 + row) * (3 * C_) + col4);
                *(float4*)&sKV[row * 64 + col4] = t4;
            }
            __syncthreads();
            for (int m = 0; m < 64; m++) {
                float d0 = 0.f, d1 = 0.f, d2 = 0.f, d3 = 0.f;
                const float* kr = &sKV[m * 64];
                #pragma unroll
                for (int e = 0; e < 64; e += 4) {
                    d0 += q[e + 0] * kr[e + 0];
                    d1 += q[e + 1] * kr[e + 1];
                    d2 += q[e + 2] * kr[e + 2];
                    d3 += q[e + 3] * kr[e + 3];
                }
                float s = ((d0 + d1) + (d2 + d3)) * scale;
                sloc[c * 64 + m] = s;
                smax = fmaxf(smax, s);
            }
        }
        float ssum = 0.0f;
        for (int m = 0; m < 256; m++) {
            float e_ = __expf(sloc[m] - smax);
            sloc[m] = e_;
            ssum += e_;
        }
        float inv = 1.0f / ssum;

        for (int c = 0; c < 4; c++) {
            __syncthreads();
            #pragma unroll
            for (int r = 0; r < 4; r++) {
                int F = threadIdx.x + 256 * r;
                int row  = F >> 4;
                int col4 = (F & 15) << 2;
                float4 t4 = *(const float4*)(vbase + (long)(c * 64 + row) * (3 * C_) + col4);
                *(float4*)&sKV[row * 64 + col4] = t4;
            }
            __syncthreads();
            for (int m = 0; m < 64; m++) {
                float pm = sloc[c * 64 + m] * inv;
                const float* vr = &sKV[m * 64];
                #pragma unroll
                for (int e = 0; e < 64; e++) ctx[e] += pm * vr[e];
            }
        }
    }

    float* outp = ctx_out + ((long)((i * B_ + b) * N_ + n)) * C_ + h * HD_;
    #pragma unroll
    for (int e4 = 0; e4 < 16; e4++) {
        float4 o4;
        o4.x = ctx[e4 * 4 + 0] * 0.25f;
        o4.y = ctx[e4 * 4 + 1] * 0.25f;
        o4.z = ctx[e4 * 4 + 2] * 0.25f;
        o4.w = ctx[e4 * 4 + 3] * 0.25f;
        *(float4*)(outp + e4 * 4) = o4;
    }
}

// ---------------- learnable-query projection ----------------
__global__ __launch_bounds__(256) void qh_kernel(
    const float* __restrict__ query, const float* __restrict__ w,
    const float* __restrict__ bq, float* __restrict__ qh)
{
    int v = blockIdx.x;
    int t = threadIdx.x;
    for (int d = t; d < C_; d += 256) {
        const float* wr = w + (long)v * (3 * C_) * C_ + (long)d * C_;
        float acc = 0.0f;
        #pragma unroll 4
        for (int c = 0; c < C_; c++) acc += query[c] * wr[c];
        qh[v * C_ + d] = acc + bq[(long)v * (3 * C_) + d];
    }
}

// ---------------- cross attention (single query) ----------------
__global__ __launch_bounds__(256) void cross_attn_kernel(
    const float* __restrict__ kv, const float* __restrict__ qh,
    float* __restrict__ c2)
{
    int h = blockIdx.x, b = blockIdx.y, v = blockIdx.z;
    int t = threadIdx.x;

    __shared__ float p[256];
    __shared__ float red[256];
    __shared__ float part[4][64];

    const float* kvb = kv + ((long)(v * B_ + b) * N_) * (2 * C_);
    const float* qhp = qh + v * C_ + h * HD_;
    const float* krow = kvb + (long)t * (2 * C_) + h * HD_;

    float s = 0.0f;
    #pragma unroll
    for (int e = 0; e < 64; e++) s += qhp[e] * krow[e];
    s *= 0.125f;

    red[t] = s; __syncthreads();
    for (int off = 128; off > 0; off >>= 1) {
        if (t < off) red[t] = fmaxf(red[t], red[t + off]);
        __syncthreads();
    }
    float mx = red[0];
    __syncthreads();

    float e_ = __expf(s - mx);
    p[t] = e_; red[t] = e_;
    __syncthreads();
    for (int off = 128; off > 0; off >>= 1) {
        if (t < off) red[t] += red[t + off];
        __syncthreads();
    }
    float inv = 1.0f / red[0];
    __syncthreads();

    int e = t & 63, pid = t >> 6;
    float acc = 0.0f;
    for (int n = pid * 64; n < pid * 64 + 64; n++)
        acc += p[n] * kvb[(long)n * (2 * C_) + C_ + h * HD_ + e];
    part[pid][e] = acc;
    __syncthreads();
    if (t < 64) {
        float r = (part[0][t] + part[1][t]) + (part[2][t] + part[3][t]);
        c2[(long)(v * B_ + b) * C_ + h * HD_ + t] = r * inv;
    }
}

// ---------------- output projection + broadcast over N ----------------
__global__ __launch_bounds__(256) void out_kernel(
    const float* __restrict__ c2, const float* __restrict__ w,
    const float* __restrict__ bias, float* __restrict__ out)
{
    int v = blockIdx.x, b = blockIdx.y;
    int t = threadIdx.x;

    __shared__ float sc[C_];
    for (int c = t; c < C_; c += 256) sc[c] = c2[(long)(v * B_ + b) * C_ + c];
    __syncthreads();

    float o[3];
    #pragma unroll
    for (int r = 0; r < 3; r++) {
        int co = t + r * 256;
        const float* wr = w + (long)v * C_ * C_ + (long)co * C_;
        float d0 = 0.f, d1 = 0.f, d2 = 0.f, d3 = 0.f;
        #pragma unroll 4
        for (int c = 0; c < C_; c += 4) {
            d0 += sc[c + 0] * wr[c + 0];
            d1 += sc[c + 1] * wr[c + 1];
            d2 += sc[c + 2] * wr[c + 2];
            d3 += sc[c + 3] * wr[c + 3];
        }
        o[r] = ((d0 + d1) + (d2 + d3)) + bias[v * C_ + co];
    }
    for (int n = 0; n < N_; n++) {
        long base = ((long)b * N_ + n) * (NVW * C_) + (long)v * C_;
        #pragma unroll
        for (int r = 0; r < 3; r++) out[base + t + r * 256] = o[r];
    }
}

// ---------------- launch ----------------
extern "C" void kernel_launch(void* const* d_in, const int* in_sizes, int n_in,
                              void* d_out, int out_size)
{
    const float* X        = (const float*)d_in[0];
    const float* norm1_g  = (const float*)d_in[1];
    const float* norm1_b  = (const float*)d_in[2];
    const float* qkv_w    = (const float*)d_in[3];
    const float* proj_w   = (const float*)d_in[4];
    const float* proj_b   = (const float*)d_in[5];
    const float* norm2_g  = (const float*)d_in[6];
    const float* norm2_b  = (const float*)d_in[7];
    const float* fc1_w    = (const float*)d_in[8];
    const float* fc1_b    = (const float*)d_in[9];
    const float* fc2_w    = (const float*)d_in[10];
    const float* fc2_b    = (const float*)d_in[11];
    const float* query    = (const float*)d_in[12];
    const float* mha_in_w = (const float*)d_in[13];
    const float* mha_in_b = (const float*)d_in[14];
    const float* mha_out_w= (const float*)d_in[15];
    const float* mha_out_b= (const float*)d_in[16];
    float* out = (float*)d_out;

    float *Xn, *qkvb, *ctx, *x, *hn, *h1, *x2, *kv, *qh, *c2;
    cudaGetSymbolAddress((void**)&Xn,   g_Xn);
    cudaGetSymbolAddress((void**)&qkvb, g_qkv);
    cudaGetSymbolAddress((void**)&ctx,  g_ctx);
    cudaGetSymbolAddress((void**)&x,    g_x);
    cudaGetSymbolAddress((void**)&hn,   g_hn);
    cudaGetSymbolAddress((void**)&h1,   g_h1);
    cudaGetSymbolAddress((void**)&x2,   g_x2);
    cudaGetSymbolAddress((void**)&kv,   g_kv);
    cudaGetSymbolAddress((void**)&qh,   g_qh);
    cudaGetSymbolAddress((void**)&c2,   g_c2);

    cudaFuncSetAttribute(gemm_mma, cudaFuncAttributeMaxDynamicSharedMemorySize,
                         GEMM_SMEM);

    const long MC  = (long)MROWS * C_;
    const long MH  = (long)MROWS * HID_;

    // 1. LN1 (remap [b*NV+v] -> [v][b]), shared params
    ln_kernel<<<NVW * B_ * N_, 256>>>(X, norm1_g, norm1_b, Xn, 1, 0);

    // 2. QKV GEMM: [1024,768] x [2304,768]^T -> [1024,2304]
    gemm_mma<<<dim3(3 * C_ / 128, MROWS / 128, NVW), 256, GEMM_SMEM>>>(
        Xn, qkv_w, nullptr, nullptr, qkvb,
        C_, 3 * C_, MC, (long)3 * C_ * C_, 0, 0, (long)MROWS * 3 * C_, 1.0f, 0);

    // 3. pairwise attention, mean over j
    attn_kernel<<<dim3(H_, B_, NVW), 256>>>(qkvb, ctx);

    // 4. proj GEMM, alpha=2 folds the residual doubling
    gemm_mma<<<dim3(C_ / 128, MROWS / 128, NVW), 256, GEMM_SMEM>>>(
        ctx, proj_w, proj_b, nullptr, x,
        C_, C_, MC, (long)C_ * C_, C_, 0, MC, 2.0f, 0);

    // 5. LN2 (per-view params)
    ln_kernel<<<NVW * B_ * N_, 256>>>(x, norm2_g, norm2_b, hn, 0, 1);

    // 6. fc1 GEMM + bias + GELU
    gemm_mma<<<dim3(HID_ / 128, MROWS / 128, NVW), 256, GEMM_SMEM>>>(
        hn, fc1_w, fc1_b, nullptr, h1,
        C_, HID_, MC, (long)HID_ * C_, HID_, 0, MH, 1.0f, 1);

    // 7. fc2 GEMM + bias + residual add (x)
    gemm_mma<<<dim3(C_ / 128, MROWS / 128, NVW), 256, GEMM_SMEM>>>(
        h1, fc2_w, fc2_b, x, x2,
        HID_, C_, MH, (long)C_ * HID_, C_, MC, MC, 1.0f, 0);

    // 8. learnable query projection
    qh_kernel<<<NVW, 256>>>(query, mha_in_w, mha_in_b, qh);

    // 9. K/V projection of x2
    gemm_mma<<<dim3(2 * C_ / 128, MROWS / 128, NVW), 256, GEMM_SMEM>>>(
        x2, mha_in_w + (long)C_ * C_, mha_in_b + C_, nullptr, kv,
        C_, 2 * C_, MC, (long)3 * C_ * C_, (long)3 * C_, 0, (long)MROWS * 2 * C_, 1.0f, 0);

    // 10. single-query cross attention -> c2[v][b][C]
    cross_attn_kernel<<<dim3(H_, B_, NVW), 256>>>(kv, qh, c2);

    // 11. output projection + broadcast over N
    out_kernel<<<dim3(NVW, B_), 256>>>(c2, mha_out_w, mha_out_b, out);
}